// round 15
// baseline (speedup 1.0000x reference)
#include <cuda_runtime.h>
#include <cuda_fp16.h>
#include <math.h>
#include <stdint.h>

// Problem constants
#define BATCH 8
#define SEQ   512
#define DMODEL 1024
#define NHEAD 16
#define DK    64
#define TBDIM 64
#define SCALE 0.125f
#define NEGINF -1e30f
#define MROWS (BATCH*SEQ)          // 4096

// ---------------------------------------------------------------------------
// Scratch (device globals)
// ---------------------------------------------------------------------------
__device__ float  g_Tb[BATCH*SEQ*SEQ];
__device__ __half g_xh[MROWS*DMODEL];
__device__ __half g_Qh[MROWS*DMODEL];
__device__ __half g_Kh[MROWS*DMODEL];
__device__ __half g_Vh[MROWS*DMODEL];
__device__ __half g_Oh[MROWS*DMODEL];
__device__ __half g_Wq[DMODEL*DMODEL];
__device__ __half g_Wk[DMODEL*DMODEL];
__device__ __half g_Wv[DMODEL*DMODEL];
__device__ __half g_Wp[DMODEL*DMODEL];

// ---------------------------------------------------------------------------
// PTX helpers
// ---------------------------------------------------------------------------
__device__ __forceinline__ uint32_t smem_u32(const void* p) {
    uint32_t a;
    asm("{ .reg .u64 t; cvta.to.shared.u64 t, %1; cvt.u32.u64 %0, t; }" : "=r"(a) : "l"(p));
    return a;
}
__device__ __forceinline__ void ldsm_x4(uint32_t (&r)[4], uint32_t addr) {
    asm volatile("ldmatrix.sync.aligned.m8n8.x4.shared.b16 {%0,%1,%2,%3}, [%4];"
        : "=r"(r[0]), "=r"(r[1]), "=r"(r[2]), "=r"(r[3]) : "r"(addr));
}
__device__ __forceinline__ void ldsm_x4t(uint32_t (&r)[4], uint32_t addr) {
    asm volatile("ldmatrix.sync.aligned.m8n8.x4.trans.shared.b16 {%0,%1,%2,%3}, [%4];"
        : "=r"(r[0]), "=r"(r[1]), "=r"(r[2]), "=r"(r[3]) : "r"(addr));
}
__device__ __forceinline__ void mma16816(float (&d)[4], const uint32_t* a,
                                         const uint32_t* b) {
    asm volatile("mma.sync.aligned.m16n8k16.row.col.f32.f16.f16.f32 "
        "{%0,%1,%2,%3}, {%4,%5,%6,%7}, {%8,%9}, {%0,%1,%2,%3};"
        : "+f"(d[0]), "+f"(d[1]), "+f"(d[2]), "+f"(d[3])
        : "r"(a[0]), "r"(a[1]), "r"(a[2]), "r"(a[3]), "r"(b[0]), "r"(b[1]));
}
// fp16-accumulate MMA (2x tensor rate on most archs)
__device__ __forceinline__ void mma16816h(uint32_t (&d)[2], const uint32_t* a,
                                          const uint32_t* b) {
    asm volatile("mma.sync.aligned.m16n8k16.row.col.f16.f16.f16.f16 "
        "{%0,%1}, {%2,%3,%4,%5}, {%6,%7}, {%0,%1};"
        : "+r"(d[0]), "+r"(d[1])
        : "r"(a[0]), "r"(a[1]), "r"(a[2]), "r"(a[3]), "r"(b[0]), "r"(b[1]));
}
__device__ __forceinline__ uint32_t ex2_h2(float a, float b) {
    __half2 h = __floats2half2_rn(a, b);
    uint32_t in = *(uint32_t*)&h, out;
    asm("ex2.approx.f16x2 %0, %1;" : "=r"(out) : "r"(in));
    return out;
}
#define CP_ASYNC16(dst, src) \
    asm volatile("cp.async.cg.shared.global [%0], [%1], 16;" :: "r"(dst), "l"(src) : "memory")
#define CP_COMMIT() asm volatile("cp.async.commit_group;" ::: "memory")
#define CP_WAIT(n)  asm volatile("cp.async.wait_group %0;" :: "n"(n) : "memory")

// ---------------------------------------------------------------------------
// Kernel 1: prep — x->fp16 + weight transposes (concurrent)
// ---------------------------------------------------------------------------
#define PREP_CONV_BLOCKS  (MROWS*DMODEL/4/256)           // 4096
#define PREP_WT_BLOCKS    (32*32*4)                      // 4096
#define PREP_BLOCKS (PREP_CONV_BLOCKS + PREP_WT_BLOCKS)

__global__ void __launch_bounds__(256) prep_kernel(
    const float* __restrict__ x,
    const float* __restrict__ wq, const float* __restrict__ wk,
    const float* __restrict__ wv, const float* __restrict__ wp)
{
    int bid = blockIdx.x;
    int tid = threadIdx.x;

    if (bid < PREP_CONV_BLOCKS) {
        int i = bid * 256 + tid;
        float4 v = ((const float4*)x)[i];
        ((__half2*)g_xh)[2*i]   = __floats2half2_rn(v.x, v.y);
        ((__half2*)g_xh)[2*i+1] = __floats2half2_rn(v.z, v.w);
    } else {
        int wb = bid - PREP_CONV_BLOCKS;
        int z  = wb >> 10;
        int by = (wb >> 5) & 31;
        int bx = wb & 31;
        const float* W = (z==0) ? wq : (z==1) ? wk : (z==2) ? wv : wp;
        __half* O      = (z==0) ? g_Wq : (z==1) ? g_Wk : (z==2) ? g_Wv : g_Wp;
        __shared__ float t[32][33];
        int kx = bx * 32, ny = by * 32;
        int tx = tid & 31, ty = tid >> 5;
#pragma unroll
        for (int i = 0; i < 4; i++)
            t[ty + i*8][tx] = W[(size_t)(kx + ty + i*8) * DMODEL + ny + tx];
        __syncthreads();
#pragma unroll
        for (int i = 0; i < 4; i++)
            O[(size_t)(ny + ty + i*8) * DMODEL + kx + tx] = __float2half(t[tx][ty + i*8]);
    }
}

// ---------------------------------------------------------------------------
// Kernel 3: HMMA GEMM with fp16-accumulate MMA (re-accumulated to fp32 per
// K=64 tile). CTA 128(M)x64(N), 4 warps (warp tile 64x32), BK=64, 3-stage
// cp.async pipeline. grid.z slice 0 computes temporal bias when mat != null.
// ---------------------------------------------------------------------------
#define ROWB 128
#define ATILEB (128*ROWB)           // 16 KB (A: 128 rows)
#define BTILEB (64*ROWB)            // 8 KB  (B: 64 rows)
#define STAGEB (ATILEB + BTILEB)    // 24 KB
#define NSTAGE 3
#define GEMM_SMEM (NSTAGE*STAGEB)   // 72 KB

__device__ __forceinline__ void store2(float* C, size_t idx, float a, float b) {
    float2 v = {a, b}; *(float2*)&C[idx] = v;
}
__device__ __forceinline__ void store2(__half* C, size_t idx, float a, float b) {
    *(__half2*)&C[idx] = __floats2half2_rn(a, b);
}

template <typename TOUT>
__global__ void __launch_bounds__(128, 3) gemm_tc(
    const __half* __restrict__ A,
    const __half* __restrict__ B0, const __half* __restrict__ B1, const __half* __restrict__ B2,
    const float* __restrict__ bi0, const float* __restrict__ bi1, const float* __restrict__ bi2,
    TOUT* __restrict__ C0, TOUT* __restrict__ C1, TOUT* __restrict__ C2,
    const float* __restrict__ mat,
    const float* __restrict__ tw1, const float* __restrict__ tb1,
    const float* __restrict__ tw2, const float* __restrict__ tb2)
{
    extern __shared__ __align__(128) unsigned char sm[];
    int tid  = threadIdx.x;

    // ---- bias slice (z==0 when mat != null) ----
    if (mat != nullptr && blockIdx.z == 0) {
        float* sw1 = (float*)sm;
        float* sb1 = sw1 + TBDIM;
        float* sw2 = sb1 + TBDIM;
        if (tid < TBDIM) { sw1[tid] = tw1[tid]; sb1[tid] = tb1[tid]; sw2[tid] = tw2[tid]; }
        __syncthreads();
        float bias0 = tb2[0];
        int bb = blockIdx.y * 16 + blockIdx.x;        // 0..511
        const float E = 2.718281828459045f;
#pragma unroll 1
        for (int it = 0; it < 8; it++) {
            int i4 = (bb * 8 + it) * 128 + tid;
            float4 mv = ((const float4*)mat)[i4];
            float t0 = 1.0f / __logf(E + mv.x);
            float t1 = 1.0f / __logf(E + mv.y);
            float t2 = 1.0f / __logf(E + mv.z);
            float t3 = 1.0f / __logf(E + mv.w);
            float a0 = bias0, a1 = a0, a2 = a0, a3 = a0;
#pragma unroll
            for (int j = 0; j < TBDIM; j++) {
                float w = sw1[j], bb2 = sb1[j], v = sw2[j];
                float h0 = fmaf(t0, w, bb2); h0 = (h0 >= 0.0f) ? h0 : 0.2f * h0;
                float h1 = fmaf(t1, w, bb2); h1 = (h1 >= 0.0f) ? h1 : 0.2f * h1;
                float h2 = fmaf(t2, w, bb2); h2 = (h2 >= 0.0f) ? h2 : 0.2f * h2;
                float h3 = fmaf(t3, w, bb2); h3 = (h3 >= 0.0f) ? h3 : 0.2f * h3;
                a0 = fmaf(h0, v, a0); a1 = fmaf(h1, v, a1);
                a2 = fmaf(h2, v, a2); a3 = fmaf(h3, v, a3);
            }
            float4 r = {a0, a1, a2, a3};
            ((float4*)g_Tb)[i4] = r;
        }
        return;
    }

    int z = blockIdx.z - (mat ? 1 : 0);
    const __half* Bt   = (z==0) ? B0  : (z==1) ? B1  : B2;
    const float*  bias = (z==0) ? bi0 : (z==1) ? bi1 : bi2;
    TOUT*         C    = (z==0) ? C0  : (z==1) ? C1  : C2;

    int lane = tid & 31;
    int wid  = tid >> 5;
    int wm   = (wid & 1) * 64;     // warp M offset (CTA M=128)
    int wn   = (wid >> 1) * 32;    // warp N offset (CTA N=64)
    int m0 = blockIdx.y * 128, n0 = blockIdx.x * 64;

    uint32_t sbase = smem_u32(sm);

    // A: 128 rows x 8 chunks = 1024 chunks, 8/thread. B: 64 rows = 512, 4/thread.
    uint32_t swoA[8];
    const __half* gA[8];
#pragma unroll
    for (int i = 0; i < 8; i++) {
        int id = tid + i * 128;
        int r = id >> 3, c = id & 7;
        swoA[i] = r * ROWB + ((c ^ (r & 7)) * 16);
        gA[i] = A + (size_t)(m0 + r) * DMODEL + c * 8;
    }
    uint32_t swoB[4];
    const __half* gB[4];
#pragma unroll
    for (int i = 0; i < 4; i++) {
        int id = tid + i * 128;
        int r = id >> 3, c = id & 7;
        swoB[i] = r * ROWB + ((c ^ (r & 7)) * 16);
        gB[i] = Bt + (size_t)(n0 + r) * DMODEL + c * 8;
    }

    float accF[4][4][4] = {};
    const int NKT = DMODEL / 64;   // 16

#pragma unroll
    for (int pf = 0; pf < 2; pf++) {
        uint32_t st = sbase + pf * STAGEB;
        int koff = pf * 64;
#pragma unroll
        for (int i = 0; i < 8; i++)
            CP_ASYNC16(st + swoA[i], gA[i] + koff);
#pragma unroll
        for (int i = 0; i < 4; i++)
            CP_ASYNC16(st + ATILEB + swoB[i], gB[i] + koff);
        CP_COMMIT();
    }

    int cur = 0;
    for (int kt = 0; kt < NKT; kt++) {
        if (kt == NKT - 1) { CP_WAIT(0); } else { CP_WAIT(1); }
        __syncthreads();

        if (kt + 2 < NKT) {
            uint32_t st = sbase + ((cur + 2 >= NSTAGE) ? (cur + 2 - NSTAGE) : (cur + 2)) * STAGEB;
            int koff = (kt + 2) * 64;
#pragma unroll
            for (int i = 0; i < 8; i++)
                CP_ASYNC16(st + swoA[i], gA[i] + koff);
#pragma unroll
            for (int i = 0; i < 4; i++)
                CP_ASYNC16(st + ATILEB + swoB[i], gB[i] + koff);
            CP_COMMIT();
        }

        uint32_t aBase = sbase + cur * STAGEB;
        uint32_t bBase = aBase + ATILEB;

        // fp16 accumulators for this K=64 tile
        uint32_t acch[4][4][2] = {};
#pragma unroll
        for (int ks = 0; ks < 4; ks++) {
            uint32_t af[4][4];
#pragma unroll
            for (int mf = 0; mf < 4; mf++) {
                int row = wm + mf * 16 + (lane & 15);
                int ch  = 2 * ks + (lane >> 4);
                ldsm_x4(af[mf], aBase + row * ROWB + ((ch ^ (row & 7)) * 16));
            }
            uint32_t bf[2][4];   // 2 pairs -> 4 n-frags
#pragma unroll
            for (int p = 0; p < 2; p++) {
                int row = wn + p * 16 + (lane & 7) + ((lane >> 4) << 3);
                int ch  = 2 * ks + ((lane >> 3) & 1);
                ldsm_x4(bf[p], bBase + row * ROWB + ((ch ^ (row & 7)) * 16));
            }
#pragma unroll
            for (int mf = 0; mf < 4; mf++)
#pragma unroll
                for (int p = 0; p < 2; p++) {
                    mma16816h(acch[mf][2*p],   af[mf], &bf[p][0]);
                    mma16816h(acch[mf][2*p+1], af[mf], &bf[p][2]);
                }
        }
        // re-accumulate into fp32
#pragma unroll
        for (int mf = 0; mf < 4; mf++)
#pragma unroll
            for (int nf = 0; nf < 4; nf++) {
                float2 f0 = __half22float2(*(__half2*)&acch[mf][nf][0]);
                float2 f1 = __half22float2(*(__half2*)&acch[mf][nf][1]);
                accF[mf][nf][0] += f0.x; accF[mf][nf][1] += f0.y;
                accF[mf][nf][2] += f1.x; accF[mf][nf][3] += f1.y;
            }
        cur = (cur + 1 >= NSTAGE) ? 0 : (cur + 1);
    }

    int g = lane >> 2, t = lane & 3;
#pragma unroll
    for (int mf = 0; mf < 4; mf++) {
        int r0 = m0 + wm + mf * 16 + g;
#pragma unroll
        for (int nf = 0; nf < 4; nf++) {
            int c = n0 + wn + nf * 8 + t * 2;
            float bx = __ldg(&bias[c]), by = __ldg(&bias[c + 1]);
            store2(C, (size_t)r0 * DMODEL + c,       accF[mf][nf][0] + bx, accF[mf][nf][1] + by);
            store2(C, (size_t)(r0 + 8) * DMODEL + c, accF[mf][nf][2] + bx, accF[mf][nf][3] + by);
        }
    }
}

// ---------------------------------------------------------------------------
// Kernel 4: HMMA causal flash attention (exact R11 config — best known).
// ---------------------------------------------------------------------------
#define LOG2E 1.4426950408889634f

__global__ void __launch_bounds__(128) attn_hmma(const int* __restrict__ pm) {
    __shared__ __align__(128) __half Qs[64*64];
    __shared__ __align__(128) __half Ks[2][64*64];
    __shared__ __align__(128) __half Vs[2][64*64];
    __shared__ int spm[2][64];

    int qt = gridDim.x - 1 - blockIdx.x;
    int h = blockIdx.y, b = blockIdx.z;
    int tid = threadIdx.x, lane = tid & 31, wid = tid >> 5;
    int wrow = wid * 16;
    int q0 = qt * 64;
    int g = lane >> 2, t = lane & 3;

    const __half* Qg = g_Qh + (size_t)b * SEQ * DMODEL + h * DK;
    const __half* Kg = g_Kh + (size_t)b * SEQ * DMODEL + h * DK;
    const __half* Vg = g_Vh + (size_t)b * SEQ * DMODEL + h * DK;
    const float* Tbb = g_Tb + (size_t)b * SEQ * SEQ;

    uint32_t qb  = smem_u32(Qs);
    uint32_t kb_[2] = { smem_u32(Ks[0]), smem_u32(Ks[1]) };
    uint32_t vb_[2] = { smem_u32(Vs[0]), smem_u32(Vs[1]) };

#pragma unroll
    for (int i = 0; i < 4; i++) {
        int id = tid + i * 128;
        int rr = id >> 3, c = id & 7;
        uint32_t sw = rr * 128 + ((c ^ (rr & 7)) * 16);
        CP_ASYNC16(qb + sw, Qg + (size_t)(q0 + rr) * DMODEL + c * 8);
        CP_ASYNC16(kb_[0] + sw, Kg + (size_t)rr * DMODEL + c * 8);
        CP_ASYNC16(vb_[0] + sw, Vg + (size_t)rr * DMODEL + c * 8);
    }
    if (tid < 16)
        CP_ASYNC16(smem_u32(spm[0]) + tid * 16, pm + b * SEQ + tid * 4);
    CP_COMMIT();

    float m0 = NEGINF, m1 = NEGINF, l0 = 0.0f, l1 = 0.0f;
    float o[8][4] = {};
    uint32_t qf[4][4];
    int qgl0 = q0 + wrow + g;
    int qgl1 = qgl0 + 8;

    const float* tb0p = &Tbb[(size_t)qgl0 * SEQ + t * 2];
    const float* tb1p = &Tbb[(size_t)qgl1 * SEQ + t * 2];

    for (int kt = 0; kt <= qt; kt++) {
        int cur = kt & 1;
        if (kt < qt) {
            int nxt = (kt + 1) & 1;
#pragma unroll
            for (int i = 0; i < 4; i++) {
                int id = tid + i * 128;
                int rr = id >> 3, c = id & 7;
                uint32_t sw = rr * 128 + ((c ^ (rr & 7)) * 16);
                CP_ASYNC16(kb_[nxt] + sw, Kg + (size_t)((kt+1)*64 + rr) * DMODEL + c * 8);
                CP_ASYNC16(vb_[nxt] + sw, Vg + (size_t)((kt+1)*64 + rr) * DMODEL + c * 8);
            }
            if (tid < 16)
                CP_ASYNC16(smem_u32(spm[nxt]) + tid * 16, pm + b * SEQ + (kt+1)*64 + tid * 4);
            CP_COMMIT();
            CP_WAIT(1);
        } else {
            CP_WAIT(0);
        }
        __syncthreads();

        if (kt == 0) {
#pragma unroll
            for (int ks = 0; ks < 4; ks++) {
                int row = wrow + (lane & 15);
                int ch  = ks * 2 + (lane >> 4);
                ldsm_x4(qf[ks], qb + row * 128 + ((ch ^ (row & 7)) * 16));
            }
        }

        float2 tbr0[8], tbr1[8];
#pragma unroll
        for (int nf = 0; nf < 8; nf++) {
            tbr0[nf] = *(const float2*)&tb0p[kt * 64 + nf * 8];
            tbr1[nf] = *(const float2*)&tb1p[kt * 64 + nf * 8];
        }

        uint32_t kb = kb_[cur], vb = vb_[cur];
        const int* pmc = spm[cur];

        float s[8][4] = {};
#pragma unroll
        for (int ks = 0; ks < 4; ks++) {
#pragma unroll
            for (int p = 0; p < 4; p++) {
                uint32_t bfr[4];
                int row = p * 16 + (lane & 7) + ((lane >> 4) << 3);
                int ch  = ks * 2 + ((lane >> 3) & 1);
                ldsm_x4(bfr, kb + row * 128 + ((ch ^ (row & 7)) * 16));
                mma16816(s[2*p],   qf[ks], &bfr[0]);
                mma16816(s[2*p+1], qf[ks], &bfr[2]);
            }
        }

        float mx0 = m0, mx1 = m1;
        if (kt == qt) {
#pragma unroll
            for (int nf = 0; nf < 8; nf++) {
                int coll = nf * 8 + t * 2;
                int kg = kt * 64 + coll;
                float v00 = fmaf(s[nf][0], SCALE, tbr0[nf].x);
                float v01 = fmaf(s[nf][1], SCALE, tbr0[nf].y);
                float v10 = fmaf(s[nf][2], SCALE, tbr1[nf].x);
                float v11 = fmaf(s[nf][3], SCALE, tbr1[nf].y);
                bool z0 = (pmc[coll] == 0), z1 = (pmc[coll + 1] == 0);
                if (z0 || kg     > qgl0) v00 = NEGINF;
                if (z1 || kg + 1 > qgl0) v01 = NEGINF;
                if (z0 || kg     > qgl1) v10 = NEGINF;
                if (z1 || kg + 1 > qgl1) v11 = NEGINF;
                s[nf][0] = v00; s[nf][1] = v01; s[nf][2] = v10; s[nf][3] = v11;
                mx0 = fmaxf(mx0, fmaxf(v00, v01));
                mx1 = fmaxf(mx1, fmaxf(v10, v11));
            }
        } else {
#pragma unroll
            for (int nf = 0; nf < 8; nf++) {
                int coll = nf * 8 + t * 2;
                float v00 = fmaf(s[nf][0], SCALE, tbr0[nf].x);
                float v01 = fmaf(s[nf][1], SCALE, tbr0[nf].y);
                float v10 = fmaf(s[nf][2], SCALE, tbr1[nf].x);
                float v11 = fmaf(s[nf][3], SCALE, tbr1[nf].y);
                if (pmc[coll] == 0)     { v00 = NEGINF; v10 = NEGINF; }
                if (pmc[coll + 1] == 0) { v01 = NEGINF; v11 = NEGINF; }
                s[nf][0] = v00; s[nf][1] = v01; s[nf][2] = v10; s[nf][3] = v11;
                mx0 = fmaxf(mx0, fmaxf(v00, v01));
                mx1 = fmaxf(mx1, fmaxf(v10, v11));
            }
        }
        mx0 = fmaxf(mx0, __shfl_xor_sync(0xffffffffu, mx0, 1));
        mx0 = fmaxf(mx0, __shfl_xor_sync(0xffffffffu, mx0, 2));
        mx1 = fmaxf(mx1, __shfl_xor_sync(0xffffffffu, mx1, 1));
        mx1 = fmaxf(mx1, __shfl_xor_sync(0xffffffffu, mx1, 2));

        float corr0 = __expf(m0 - mx0);
        float corr1 = __expf(m1 - mx1);
        m0 = mx0; m1 = mx1;

        float mxl0 = mx0 * LOG2E, mxl1 = mx1 * LOG2E;
        float sum0 = 0.0f, sum1 = 0.0f;
        uint32_t pa[4][4];
#pragma unroll
        for (int nf = 0; nf < 8; nf++) {
            uint32_t p0 = ex2_h2(fmaf(s[nf][0], LOG2E, -mxl0),
                                 fmaf(s[nf][1], LOG2E, -mxl0));
            uint32_t p1 = ex2_h2(fmaf(s[nf][2], LOG2E, -mxl1),
                                 fmaf(s[nf][3], LOG2E, -mxl1));
            pa[nf >> 1][(nf & 1) * 2 + 0] = p0;
            pa[nf >> 1][(nf & 1) * 2 + 1] = p1;
            float2 f0 = __half22float2(*(__half2*)&p0);
            float2 f1 = __half22float2(*(__half2*)&p1);
            sum0 += f0.x + f0.y;
            sum1 += f1.x + f1.y;
        }
        sum0 += __shfl_xor_sync(0xffffffffu, sum0, 1);
        sum0 += __shfl_xor_sync(0xffffffffu, sum0, 2);
        sum1 += __shfl_xor_sync(0xffffffffu, sum1, 1);
        sum1 += __shfl_xor_sync(0xffffffffu, sum1, 2);
        l0 = l0 * corr0 + sum0;
        l1 = l1 * corr1 + sum1;

#pragma unroll
        for (int nf = 0; nf < 8; nf++) {
            o[nf][0] *= corr0; o[nf][1] *= corr0;
            o[nf][2] *= corr1; o[nf][3] *= corr1;
        }

#pragma unroll
        for (int kk = 0; kk < 4; kk++) {
#pragma unroll
            for (int p = 0; p < 4; p++) {
                uint32_t bfr[4];
                int row = kk * 16 + (lane & 7) + (((lane >> 3) & 1) << 3);
                int ch  = p * 2 + ((lane >> 4) & 1);
                ldsm_x4t(bfr, vb + row * 128 + ((ch ^ (row & 7)) * 16));
                mma16816(o[2*p],   pa[kk], &bfr[0]);
                mma16816(o[2*p+1], pa[kk], &bfr[2]);
            }
        }
        __syncthreads();
    }

    float inv0 = 1.0f / l0, inv1 = 1.0f / l1;
    __half* Og = g_Oh + (size_t)b * SEQ * DMODEL + h * DK;
#pragma unroll
    for (int nf = 0; nf < 8; nf++) {
        int coll = nf * 8 + t * 2;
        *(__half2*)&Og[(size_t)(q0 + wrow + g) * DMODEL + coll] =
            __floats2half2_rn(o[nf][0] * inv0, o[nf][1] * inv0);
        *(__half2*)&Og[(size_t)(q0 + wrow + g + 8) * DMODEL + coll] =
            __floats2half2_rn(o[nf][2] * inv1, o[nf][3] * inv1);
    }
}

// ---------------------------------------------------------------------------
extern "C" void kernel_launch(void* const* d_in, const int* in_sizes, int n_in,
                              void* d_out, int out_size) {
    const float* x      = (const float*)d_in[0];
    const int*   pm     = (const int*)  d_in[1];
    const float* mat    = (const float*)d_in[2];
    const float* wq     = (const float*)d_in[3];
    const float* bq     = (const float*)d_in[4];
    const float* wk     = (const float*)d_in[5];
    const float* bk     = (const float*)d_in[6];
    const float* wv     = (const float*)d_in[7];
    const float* bv     = (const float*)d_in[8];
    const float* w_proj = (const float*)d_in[9];
    const float* b_proj = (const float*)d_in[10];
    const float* w_tb1  = (const float*)d_in[11];
    const float* b_tb1  = (const float*)d_in[12];
    const float* w_tb2  = (const float*)d_in[13];
    const float* b_tb2  = (const float*)d_in[14];
    float* out = (float*)d_out;

    __half *xh, *Oh, *Wq, *Wk, *Wv, *Wp, *Qh, *Kh, *Vh;
    cudaGetSymbolAddress((void**)&xh, g_xh);
    cudaGetSymbolAddress((void**)&Oh, g_Oh);
    cudaGetSymbolAddress((void**)&Wq, g_Wq);
    cudaGetSymbolAddress((void**)&Wk, g_Wk);
    cudaGetSymbolAddress((void**)&Wv, g_Wv);
    cudaGetSymbolAddress((void**)&Wp, g_Wp);
    cudaGetSymbolAddress((void**)&Qh, g_Qh);
    cudaGetSymbolAddress((void**)&Kh, g_Kh);
    cudaGetSymbolAddress((void**)&Vh, g_Vh);

    cudaFuncSetAttribute(gemm_tc<__half>, cudaFuncAttributeMaxDynamicSharedMemorySize, GEMM_SMEM);
    cudaFuncSetAttribute(gemm_tc<float>,  cudaFuncAttributeMaxDynamicSharedMemorySize, GEMM_SMEM);

    // 1) prep: x->fp16 + weight transposes (concurrent)
    prep_kernel<<<PREP_BLOCKS, 256>>>(x, wq, wk, wv, w_proj);

    // 2) QKV projections (fp16-acc HMMA) + temporal bias in grid.z slice 0
    gemm_tc<__half><<<dim3(DMODEL/64, MROWS/128, 4), 128, GEMM_SMEM>>>(
        xh, Wq, Wk, Wv, bq, bk, bv, Qh, Kh, Vh,
        mat, w_tb1, b_tb1, w_tb2, b_tb2);

    // 3) HMMA flash attention (exact R11 config)
    attn_hmma<<<dim3(SEQ/64, NHEAD, BATCH), 128>>>(pm);

    // 4) output projection (fp16-acc HMMA, fp32 out)
    gemm_tc<float><<<dim3(DMODEL/64, MROWS/128, 1), 128, GEMM_SMEM>>>(
        Oh, Wp, Wp, Wp, b_proj, b_proj, b_proj, out, out, out,
        nullptr, nullptr, nullptr, nullptr, nullptr);
}

// round 16
// speedup vs baseline: 1.1557x; 1.1557x over previous
#include <cuda_runtime.h>
#include <cuda_fp16.h>
#include <math.h>
#include <stdint.h>

// Problem constants
#define BATCH 8
#define SEQ   512
#define DMODEL 1024
#define NHEAD 16
#define DK    64
#define TBDIM 64
#define SCALE 0.125f
#define NEGINF -1e30f
#define MROWS (BATCH*SEQ)          // 4096

// ---------------------------------------------------------------------------
// Scratch (device globals)
// ---------------------------------------------------------------------------
__device__ float  g_Tb[BATCH*SEQ*SEQ];      // temporal bias (B,S,S) fp32
__device__ __half g_xh[MROWS*DMODEL];       // x in fp16
__device__ __half g_Qh[MROWS*DMODEL];       // Q (B,S,D) fp16, head h at col h*64
__device__ __half g_Kh[MROWS*DMODEL];
__device__ __half g_Vh[MROWS*DMODEL];
__device__ __half g_Oh[MROWS*DMODEL];       // attention output fp16
__device__ __half g_Wq[DMODEL*DMODEL];      // W^T fp16: [N][K]
__device__ __half g_Wk[DMODEL*DMODEL];
__device__ __half g_Wv[DMODEL*DMODEL];
__device__ __half g_Wp[DMODEL*DMODEL];

// ---------------------------------------------------------------------------
// PTX helpers
// ---------------------------------------------------------------------------
__device__ __forceinline__ uint32_t smem_u32(const void* p) {
    uint32_t a;
    asm("{ .reg .u64 t; cvta.to.shared.u64 t, %1; cvt.u32.u64 %0, t; }" : "=r"(a) : "l"(p));
    return a;
}
__device__ __forceinline__ void ldsm_x4(uint32_t (&r)[4], uint32_t addr) {
    asm volatile("ldmatrix.sync.aligned.m8n8.x4.shared.b16 {%0,%1,%2,%3}, [%4];"
        : "=r"(r[0]), "=r"(r[1]), "=r"(r[2]), "=r"(r[3]) : "r"(addr));
}
__device__ __forceinline__ void ldsm_x4t(uint32_t (&r)[4], uint32_t addr) {
    asm volatile("ldmatrix.sync.aligned.m8n8.x4.trans.shared.b16 {%0,%1,%2,%3}, [%4];"
        : "=r"(r[0]), "=r"(r[1]), "=r"(r[2]), "=r"(r[3]) : "r"(addr));
}
__device__ __forceinline__ void mma16816(float (&d)[4], const uint32_t* a,
                                         const uint32_t* b) {
    asm volatile("mma.sync.aligned.m16n8k16.row.col.f32.f16.f16.f32 "
        "{%0,%1,%2,%3}, {%4,%5,%6,%7}, {%8,%9}, {%0,%1,%2,%3};"
        : "+f"(d[0]), "+f"(d[1]), "+f"(d[2]), "+f"(d[3])
        : "r"(a[0]), "r"(a[1]), "r"(a[2]), "r"(a[3]), "r"(b[0]), "r"(b[1]));
}
__device__ __forceinline__ uint32_t ex2_h2(float a, float b) {
    __half2 h = __floats2half2_rn(a, b);
    uint32_t in = *(uint32_t*)&h, out;
    asm("ex2.approx.f16x2 %0, %1;" : "=r"(out) : "r"(in));
    return out;
}
#define CP_ASYNC16(dst, src) \
    asm volatile("cp.async.cg.shared.global [%0], [%1], 16;" :: "r"(dst), "l"(src) : "memory")
#define CP_COMMIT() asm volatile("cp.async.commit_group;" ::: "memory")
#define CP_WAIT(n)  asm volatile("cp.async.wait_group %0;" :: "n"(n) : "memory")

// ---------------------------------------------------------------------------
// Kernel 1: prep — x->fp16 + weight transposes (concurrent; bias moved into
// the QKV GEMM launch)
// ---------------------------------------------------------------------------
#define PREP_CONV_BLOCKS  (MROWS*DMODEL/4/256)           // 4096
#define PREP_WT_BLOCKS    (32*32*4)                      // 4096
#define PREP_BLOCKS (PREP_CONV_BLOCKS + PREP_WT_BLOCKS)

__global__ void __launch_bounds__(256) prep_kernel(
    const float* __restrict__ x,
    const float* __restrict__ wq, const float* __restrict__ wk,
    const float* __restrict__ wv, const float* __restrict__ wp)
{
    int bid = blockIdx.x;
    int tid = threadIdx.x;

    if (bid < PREP_CONV_BLOCKS) {
        int i = bid * 256 + tid;
        float4 v = ((const float4*)x)[i];
        ((__half2*)g_xh)[2*i]   = __floats2half2_rn(v.x, v.y);
        ((__half2*)g_xh)[2*i+1] = __floats2half2_rn(v.z, v.w);
    } else {
        int wb = bid - PREP_CONV_BLOCKS;
        int z  = wb >> 10;
        int by = (wb >> 5) & 31;
        int bx = wb & 31;
        const float* W = (z==0) ? wq : (z==1) ? wk : (z==2) ? wv : wp;
        __half* O      = (z==0) ? g_Wq : (z==1) ? g_Wk : (z==2) ? g_Wv : g_Wp;
        __shared__ float t[32][33];
        int kx = bx * 32, ny = by * 32;
        int tx = tid & 31, ty = tid >> 5;
#pragma unroll
        for (int i = 0; i < 4; i++)
            t[ty + i*8][tx] = W[(size_t)(kx + ty + i*8) * DMODEL + ny + tx];
        __syncthreads();
#pragma unroll
        for (int i = 0; i < 4; i++)
            O[(size_t)(ny + ty + i*8) * DMODEL + kx + tx] = __float2half(t[tx][ty + i*8]);
    }
}

// ---------------------------------------------------------------------------
// Kernel 3: HMMA GEMM, CTA 128x128, 4 warps, warp tile 64x64, BK=64,
// 3-stage cp.async pipeline. grid.z slice 0 computes temporal bias when
// `mat` is non-null (hidden under the tensor-bound GEMM slices).
// ---------------------------------------------------------------------------
#define ROWB 128
#define TILEB (128*ROWB)
#define NSTAGE 3
#define GEMM_SMEM (NSTAGE*2*TILEB)  // 96 KB

__device__ __forceinline__ void store2(float* C, size_t idx, float a, float b) {
    float2 v = {a, b}; *(float2*)&C[idx] = v;
}
__device__ __forceinline__ void store2(__half* C, size_t idx, float a, float b) {
    *(__half2*)&C[idx] = __floats2half2_rn(a, b);
}

template <typename TOUT>
__global__ void __launch_bounds__(128, 2) gemm_tc(
    const __half* __restrict__ A,
    const __half* __restrict__ B0, const __half* __restrict__ B1, const __half* __restrict__ B2,
    const float* __restrict__ bi0, const float* __restrict__ bi1, const float* __restrict__ bi2,
    TOUT* __restrict__ C0, TOUT* __restrict__ C1, TOUT* __restrict__ C2,
    const float* __restrict__ mat,
    const float* __restrict__ tw1, const float* __restrict__ tb1,
    const float* __restrict__ tw2, const float* __restrict__ tb2)
{
    extern __shared__ __align__(128) unsigned char sm[];
    int tid  = threadIdx.x;

    // ---- bias slice (z==0 when mat != null): temporal bias precompute ----
    if (mat != nullptr && blockIdx.z == 0) {
        float* sw1 = (float*)sm;
        float* sb1 = sw1 + TBDIM;
        float* sw2 = sb1 + TBDIM;
        if (tid < TBDIM) { sw1[tid] = tw1[tid]; sb1[tid] = tb1[tid]; sw2[tid] = tw2[tid]; }
        __syncthreads();
        float bias0 = tb2[0];
        int bb = blockIdx.y * 8 + blockIdx.x;        // 0..255
        const float E = 2.718281828459045f;
#pragma unroll 1
        for (int it = 0; it < 16; it++) {
            int i4 = (bb * 16 + it) * 128 + tid;
            float4 mv = ((const float4*)mat)[i4];
            float t0 = 1.0f / __logf(E + mv.x);
            float t1 = 1.0f / __logf(E + mv.y);
            float t2 = 1.0f / __logf(E + mv.z);
            float t3 = 1.0f / __logf(E + mv.w);
            float a0 = bias0, a1 = a0, a2 = a0, a3 = a0;
#pragma unroll
            for (int j = 0; j < TBDIM; j++) {
                float w = sw1[j], bb2 = sb1[j], v = sw2[j];
                float h0 = fmaf(t0, w, bb2); h0 = (h0 >= 0.0f) ? h0 : 0.2f * h0;
                float h1 = fmaf(t1, w, bb2); h1 = (h1 >= 0.0f) ? h1 : 0.2f * h1;
                float h2 = fmaf(t2, w, bb2); h2 = (h2 >= 0.0f) ? h2 : 0.2f * h2;
                float h3 = fmaf(t3, w, bb2); h3 = (h3 >= 0.0f) ? h3 : 0.2f * h3;
                a0 = fmaf(h0, v, a0); a1 = fmaf(h1, v, a1);
                a2 = fmaf(h2, v, a2); a3 = fmaf(h3, v, a3);
            }
            float4 r = {a0, a1, a2, a3};
            ((float4*)g_Tb)[i4] = r;
        }
        return;
    }

    int z = blockIdx.z - (mat ? 1 : 0);
    const __half* Bt   = (z==0) ? B0  : (z==1) ? B1  : B2;
    const float*  bias = (z==0) ? bi0 : (z==1) ? bi1 : bi2;
    TOUT*         C    = (z==0) ? C0  : (z==1) ? C1  : C2;

    int lane = tid & 31;
    int wid  = tid >> 5;
    int wm   = (wid & 1) * 64;
    int wn   = (wid >> 1) * 64;
    int m0 = blockIdx.y * 128, n0 = blockIdx.x * 128;

    uint32_t sbase = smem_u32(sm);

    uint32_t swo[8];
    const __half *gA[8], *gB[8];
#pragma unroll
    for (int i = 0; i < 8; i++) {
        int id = tid + i * 128;
        int r = id >> 3, c = id & 7;
        swo[i] = r * ROWB + ((c ^ (r & 7)) * 16);
        gA[i] = A  + (size_t)(m0 + r) * DMODEL + c * 8;
        gB[i] = Bt + (size_t)(n0 + r) * DMODEL + c * 8;
    }

    float acc[4][8][4] = {};
    const int NKT = DMODEL / 64;

#pragma unroll
    for (int pf = 0; pf < 2; pf++) {
        uint32_t ab = sbase + pf * 2 * TILEB;
        int koff = pf * 64;
#pragma unroll
        for (int i = 0; i < 8; i++) {
            CP_ASYNC16(ab + swo[i],         gA[i] + koff);
            CP_ASYNC16(ab + TILEB + swo[i], gB[i] + koff);
        }
        CP_COMMIT();
    }

    int cur = 0;
    for (int kt = 0; kt < NKT; kt++) {
        if (kt == NKT - 1) { CP_WAIT(0); } else { CP_WAIT(1); }
        __syncthreads();

        if (kt + 2 < NKT) {
            uint32_t ab = sbase + ((cur + 2 >= NSTAGE) ? (cur + 2 - NSTAGE) : (cur + 2)) * 2 * TILEB;
            int koff = (kt + 2) * 64;
#pragma unroll
            for (int i = 0; i < 8; i++) {
                CP_ASYNC16(ab + swo[i],         gA[i] + koff);
                CP_ASYNC16(ab + TILEB + swo[i], gB[i] + koff);
            }
            CP_COMMIT();
        }

        uint32_t aBase = sbase + cur * 2 * TILEB;
        uint32_t bBase = aBase + TILEB;

#pragma unroll
        for (int ks = 0; ks < 4; ks++) {
            uint32_t af[4][4];
#pragma unroll
            for (int mf = 0; mf < 4; mf++) {
                int row = wm + mf * 16 + (lane & 15);
                int ch  = 2 * ks + (lane >> 4);
                ldsm_x4(af[mf], aBase + row * ROWB + ((ch ^ (row & 7)) * 16));
            }
            uint32_t bf[4][4];
#pragma unroll
            for (int p = 0; p < 4; p++) {
                int row = wn + p * 16 + (lane & 7) + ((lane >> 4) << 3);
                int ch  = 2 * ks + ((lane >> 3) & 1);
                ldsm_x4(bf[p], bBase + row * ROWB + ((ch ^ (row & 7)) * 16));
            }
#pragma unroll
            for (int mf = 0; mf < 4; mf++)
#pragma unroll
                for (int p = 0; p < 4; p++) {
                    mma16816(acc[mf][2*p],   af[mf], &bf[p][0]);
                    mma16816(acc[mf][2*p+1], af[mf], &bf[p][2]);
                }
        }
        cur = (cur + 1 >= NSTAGE) ? 0 : (cur + 1);
    }

    int g = lane >> 2, t = lane & 3;
#pragma unroll
    for (int mf = 0; mf < 4; mf++) {
        int r0 = m0 + wm + mf * 16 + g;
#pragma unroll
        for (int nf = 0; nf < 8; nf++) {
            int c = n0 + wn + nf * 8 + t * 2;
            float bx = __ldg(&bias[c]), by = __ldg(&bias[c + 1]);
            store2(C, (size_t)r0 * DMODEL + c,       acc[mf][nf][0] + bx, acc[mf][nf][1] + by);
            store2(C, (size_t)(r0 + 8) * DMODEL + c, acc[mf][nf][2] + bx, acc[mf][nf][3] + by);
        }
    }
}

// ---------------------------------------------------------------------------
// Kernel 4: HMMA causal flash attention (R11 configuration — best known).
// Q frags + Tb hoisted; diag-only causal mask; f16x2 ex2 softmax.
// ---------------------------------------------------------------------------
#define LOG2E 1.4426950408889634f

__global__ void __launch_bounds__(128) attn_hmma(const int* __restrict__ pm) {
    __shared__ __align__(128) __half Qs[64*64];
    __shared__ __align__(128) __half Ks[2][64*64];
    __shared__ __align__(128) __half Vs[2][64*64];
    __shared__ int spm[2][64];

    int qt = gridDim.x - 1 - blockIdx.x;      // long blocks first
    int h = blockIdx.y, b = blockIdx.z;
    int tid = threadIdx.x, lane = tid & 31, wid = tid >> 5;
    int wrow = wid * 16;
    int q0 = qt * 64;
    int g = lane >> 2, t = lane & 3;

    const __half* Qg = g_Qh + (size_t)b * SEQ * DMODEL + h * DK;
    const __half* Kg = g_Kh + (size_t)b * SEQ * DMODEL + h * DK;
    const __half* Vg = g_Vh + (size_t)b * SEQ * DMODEL + h * DK;
    const float* Tbb = g_Tb + (size_t)b * SEQ * SEQ;

    uint32_t qb  = smem_u32(Qs);
    uint32_t kb_[2] = { smem_u32(Ks[0]), smem_u32(Ks[1]) };
    uint32_t vb_[2] = { smem_u32(Vs[0]), smem_u32(Vs[1]) };

#pragma unroll
    for (int i = 0; i < 4; i++) {
        int id = tid + i * 128;
        int rr = id >> 3, c = id & 7;
        uint32_t sw = rr * 128 + ((c ^ (rr & 7)) * 16);
        CP_ASYNC16(qb + sw, Qg + (size_t)(q0 + rr) * DMODEL + c * 8);
        CP_ASYNC16(kb_[0] + sw, Kg + (size_t)rr * DMODEL + c * 8);
        CP_ASYNC16(vb_[0] + sw, Vg + (size_t)rr * DMODEL + c * 8);
    }
    if (tid < 16)
        CP_ASYNC16(smem_u32(spm[0]) + tid * 16, pm + b * SEQ + tid * 4);
    CP_COMMIT();

    float m0 = NEGINF, m1 = NEGINF, l0 = 0.0f, l1 = 0.0f;
    float o[8][4] = {};
    uint32_t qf[4][4];
    int qgl0 = q0 + wrow + g;
    int qgl1 = qgl0 + 8;

    const float* tb0p = &Tbb[(size_t)qgl0 * SEQ + t * 2];
    const float* tb1p = &Tbb[(size_t)qgl1 * SEQ + t * 2];

    for (int kt = 0; kt <= qt; kt++) {
        int cur = kt & 1;
        if (kt < qt) {
            int nxt = (kt + 1) & 1;
#pragma unroll
            for (int i = 0; i < 4; i++) {
                int id = tid + i * 128;
                int rr = id >> 3, c = id & 7;
                uint32_t sw = rr * 128 + ((c ^ (rr & 7)) * 16);
                CP_ASYNC16(kb_[nxt] + sw, Kg + (size_t)((kt+1)*64 + rr) * DMODEL + c * 8);
                CP_ASYNC16(vb_[nxt] + sw, Vg + (size_t)((kt+1)*64 + rr) * DMODEL + c * 8);
            }
            if (tid < 16)
                CP_ASYNC16(smem_u32(spm[nxt]) + tid * 16, pm + b * SEQ + (kt+1)*64 + tid * 4);
            CP_COMMIT();
            CP_WAIT(1);
        } else {
            CP_WAIT(0);
        }
        __syncthreads();

        if (kt == 0) {
#pragma unroll
            for (int ks = 0; ks < 4; ks++) {
                int row = wrow + (lane & 15);
                int ch  = ks * 2 + (lane >> 4);
                ldsm_x4(qf[ks], qb + row * 128 + ((ch ^ (row & 7)) * 16));
            }
        }

        // ---- hoisted Tb loads (latency hidden under S-mma below) ----
        float2 tbr0[8], tbr1[8];
#pragma unroll
        for (int nf = 0; nf < 8; nf++) {
            tbr0[nf] = *(const float2*)&tb0p[kt * 64 + nf * 8];
            tbr1[nf] = *(const float2*)&tb1p[kt * 64 + nf * 8];
        }

        uint32_t kb = kb_[cur], vb = vb_[cur];
        const int* pmc = spm[cur];

        // ---- S = Q K^T ----
        float s[8][4] = {};
#pragma unroll
        for (int ks = 0; ks < 4; ks++) {
#pragma unroll
            for (int p = 0; p < 4; p++) {
                uint32_t bfr[4];
                int row = p * 16 + (lane & 7) + ((lane >> 4) << 3);
                int ch  = ks * 2 + ((lane >> 3) & 1);
                ldsm_x4(bfr, kb + row * 128 + ((ch ^ (row & 7)) * 16));
                mma16816(s[2*p],   qf[ks], &bfr[0]);
                mma16816(s[2*p+1], qf[ks], &bfr[2]);
            }
        }

        // ---- scale + bias + masks + row max ----
        float mx0 = m0, mx1 = m1;
        if (kt == qt) {
#pragma unroll
            for (int nf = 0; nf < 8; nf++) {
                int coll = nf * 8 + t * 2;
                int kg = kt * 64 + coll;
                float v00 = fmaf(s[nf][0], SCALE, tbr0[nf].x);
                float v01 = fmaf(s[nf][1], SCALE, tbr0[nf].y);
                float v10 = fmaf(s[nf][2], SCALE, tbr1[nf].x);
                float v11 = fmaf(s[nf][3], SCALE, tbr1[nf].y);
                bool z0 = (pmc[coll] == 0), z1 = (pmc[coll + 1] == 0);
                if (z0 || kg     > qgl0) v00 = NEGINF;
                if (z1 || kg + 1 > qgl0) v01 = NEGINF;
                if (z0 || kg     > qgl1) v10 = NEGINF;
                if (z1 || kg + 1 > qgl1) v11 = NEGINF;
                s[nf][0] = v00; s[nf][1] = v01; s[nf][2] = v10; s[nf][3] = v11;
                mx0 = fmaxf(mx0, fmaxf(v00, v01));
                mx1 = fmaxf(mx1, fmaxf(v10, v11));
            }
        } else {
#pragma unroll
            for (int nf = 0; nf < 8; nf++) {
                int coll = nf * 8 + t * 2;
                float v00 = fmaf(s[nf][0], SCALE, tbr0[nf].x);
                float v01 = fmaf(s[nf][1], SCALE, tbr0[nf].y);
                float v10 = fmaf(s[nf][2], SCALE, tbr1[nf].x);
                float v11 = fmaf(s[nf][3], SCALE, tbr1[nf].y);
                if (pmc[coll] == 0)     { v00 = NEGINF; v10 = NEGINF; }
                if (pmc[coll + 1] == 0) { v01 = NEGINF; v11 = NEGINF; }
                s[nf][0] = v00; s[nf][1] = v01; s[nf][2] = v10; s[nf][3] = v11;
                mx0 = fmaxf(mx0, fmaxf(v00, v01));
                mx1 = fmaxf(mx1, fmaxf(v10, v11));
            }
        }
        mx0 = fmaxf(mx0, __shfl_xor_sync(0xffffffffu, mx0, 1));
        mx0 = fmaxf(mx0, __shfl_xor_sync(0xffffffffu, mx0, 2));
        mx1 = fmaxf(mx1, __shfl_xor_sync(0xffffffffu, mx1, 1));
        mx1 = fmaxf(mx1, __shfl_xor_sync(0xffffffffu, mx1, 2));

        float corr0 = __expf(m0 - mx0);
        float corr1 = __expf(m1 - mx1);
        m0 = mx0; m1 = mx1;

        // ---- exponentiate (packed fp16 ex2) -> P frags + row sums ----
        float mxl0 = mx0 * LOG2E, mxl1 = mx1 * LOG2E;
        float sum0 = 0.0f, sum1 = 0.0f;
        uint32_t pa[4][4];
#pragma unroll
        for (int nf = 0; nf < 8; nf++) {
            uint32_t p0 = ex2_h2(fmaf(s[nf][0], LOG2E, -mxl0),
                                 fmaf(s[nf][1], LOG2E, -mxl0));
            uint32_t p1 = ex2_h2(fmaf(s[nf][2], LOG2E, -mxl1),
                                 fmaf(s[nf][3], LOG2E, -mxl1));
            pa[nf >> 1][(nf & 1) * 2 + 0] = p0;
            pa[nf >> 1][(nf & 1) * 2 + 1] = p1;
            float2 f0 = __half22float2(*(__half2*)&p0);
            float2 f1 = __half22float2(*(__half2*)&p1);
            sum0 += f0.x + f0.y;
            sum1 += f1.x + f1.y;
        }
        sum0 += __shfl_xor_sync(0xffffffffu, sum0, 1);
        sum0 += __shfl_xor_sync(0xffffffffu, sum0, 2);
        sum1 += __shfl_xor_sync(0xffffffffu, sum1, 1);
        sum1 += __shfl_xor_sync(0xffffffffu, sum1, 2);
        l0 = l0 * corr0 + sum0;
        l1 = l1 * corr1 + sum1;

#pragma unroll
        for (int nf = 0; nf < 8; nf++) {
            o[nf][0] *= corr0; o[nf][1] *= corr0;
            o[nf][2] *= corr1; o[nf][3] *= corr1;
        }

        // ---- O += P V ----
#pragma unroll
        for (int kk = 0; kk < 4; kk++) {
#pragma unroll
            for (int p = 0; p < 4; p++) {
                uint32_t bfr[4];
                int row = kk * 16 + (lane & 7) + (((lane >> 3) & 1) << 3);
                int ch  = p * 2 + ((lane >> 4) & 1);
                ldsm_x4t(bfr, vb + row * 128 + ((ch ^ (row & 7)) * 16));
                mma16816(o[2*p],   pa[kk], &bfr[0]);
                mma16816(o[2*p+1], pa[kk], &bfr[2]);
            }
        }
        __syncthreads();
    }

    float inv0 = 1.0f / l0, inv1 = 1.0f / l1;
    __half* Og = g_Oh + (size_t)b * SEQ * DMODEL + h * DK;
#pragma unroll
    for (int nf = 0; nf < 8; nf++) {
        int coll = nf * 8 + t * 2;
        *(__half2*)&Og[(size_t)(q0 + wrow + g) * DMODEL + coll] =
            __floats2half2_rn(o[nf][0] * inv0, o[nf][1] * inv0);
        *(__half2*)&Og[(size_t)(q0 + wrow + g + 8) * DMODEL + coll] =
            __floats2half2_rn(o[nf][2] * inv1, o[nf][3] * inv1);
    }
}

// ---------------------------------------------------------------------------
extern "C" void kernel_launch(void* const* d_in, const int* in_sizes, int n_in,
                              void* d_out, int out_size) {
    const float* x      = (const float*)d_in[0];
    const int*   pm     = (const int*)  d_in[1];
    const float* mat    = (const float*)d_in[2];
    const float* wq     = (const float*)d_in[3];
    const float* bq     = (const float*)d_in[4];
    const float* wk     = (const float*)d_in[5];
    const float* bk     = (const float*)d_in[6];
    const float* wv     = (const float*)d_in[7];
    const float* bv     = (const float*)d_in[8];
    const float* w_proj = (const float*)d_in[9];
    const float* b_proj = (const float*)d_in[10];
    const float* w_tb1  = (const float*)d_in[11];
    const float* b_tb1  = (const float*)d_in[12];
    const float* w_tb2  = (const float*)d_in[13];
    const float* b_tb2  = (const float*)d_in[14];
    float* out = (float*)d_out;

    __half *xh, *Oh, *Wq, *Wk, *Wv, *Wp, *Qh, *Kh, *Vh;
    cudaGetSymbolAddress((void**)&xh, g_xh);
    cudaGetSymbolAddress((void**)&Oh, g_Oh);
    cudaGetSymbolAddress((void**)&Wq, g_Wq);
    cudaGetSymbolAddress((void**)&Wk, g_Wk);
    cudaGetSymbolAddress((void**)&Wv, g_Wv);
    cudaGetSymbolAddress((void**)&Wp, g_Wp);
    cudaGetSymbolAddress((void**)&Qh, g_Qh);
    cudaGetSymbolAddress((void**)&Kh, g_Kh);
    cudaGetSymbolAddress((void**)&Vh, g_Vh);

    cudaFuncSetAttribute(gemm_tc<__half>, cudaFuncAttributeMaxDynamicSharedMemorySize, GEMM_SMEM);
    cudaFuncSetAttribute(gemm_tc<float>,  cudaFuncAttributeMaxDynamicSharedMemorySize, GEMM_SMEM);

    // 1) prep: x->fp16 + weight transposes (concurrent)
    prep_kernel<<<PREP_BLOCKS, 256>>>(x, wq, wk, wv, w_proj);

    // 2) QKV projections (HMMA, fp16 out) + temporal bias in grid.z slice 0
    gemm_tc<__half><<<dim3(DMODEL/128, MROWS/128, 4), 128, GEMM_SMEM>>>(
        xh, Wq, Wk, Wv, bq, bk, bv, Qh, Kh, Vh,
        mat, w_tb1, b_tb1, w_tb2, b_tb2);

    // 3) HMMA flash attention (fp16 out, long blocks first)
    attn_hmma<<<dim3(SEQ/64, NHEAD, BATCH), 128>>>(pm);

    // 4) output projection (HMMA, fp32 out; no bias slice)
    gemm_tc<float><<<dim3(DMODEL/128, MROWS/128, 1), 128, GEMM_SMEM>>>(
        Oh, Wp, Wp, Wp, b_proj, b_proj, b_proj, out, out, out,
        nullptr, nullptr, nullptr, nullptr, nullptr);
}

// round 17
// speedup vs baseline: 1.1674x; 1.0101x over previous
#include <cuda_runtime.h>
#include <cuda_fp16.h>
#include <math.h>
#include <stdint.h>

// Problem constants
#define BATCH 8
#define SEQ   512
#define DMODEL 1024
#define NHEAD 16
#define DK    64
#define TBDIM 64
#define SCALE 0.125f
#define NEGINF -1e30f
#define MROWS (BATCH*SEQ)          // 4096

// ---------------------------------------------------------------------------
// Scratch (device globals)
// ---------------------------------------------------------------------------
__device__ float  g_Tb[BATCH*SEQ*SEQ];      // temporal bias (B,S,S) fp32
__device__ __half g_xh[MROWS*DMODEL];       // x in fp16
__device__ __half g_Qh[MROWS*DMODEL];       // Q (B,S,D) fp16, head h at col h*64
__device__ __half g_Kh[MROWS*DMODEL];
__device__ __half g_Vh[MROWS*DMODEL];
__device__ __half g_Oh[MROWS*DMODEL];       // attention output fp16
__device__ __half g_Wq[DMODEL*DMODEL];      // W^T fp16: [N][K]
__device__ __half g_Wk[DMODEL*DMODEL];
__device__ __half g_Wv[DMODEL*DMODEL];
__device__ __half g_Wp[DMODEL*DMODEL];

// ---------------------------------------------------------------------------
// PTX helpers
// ---------------------------------------------------------------------------
__device__ __forceinline__ uint32_t smem_u32(const void* p) {
    uint32_t a;
    asm("{ .reg .u64 t; cvta.to.shared.u64 t, %1; cvt.u32.u64 %0, t; }" : "=r"(a) : "l"(p));
    return a;
}
__device__ __forceinline__ void ldsm_x4(uint32_t (&r)[4], uint32_t addr) {
    asm volatile("ldmatrix.sync.aligned.m8n8.x4.shared.b16 {%0,%1,%2,%3}, [%4];"
        : "=r"(r[0]), "=r"(r[1]), "=r"(r[2]), "=r"(r[3]) : "r"(addr));
}
__device__ __forceinline__ void ldsm_x4t(uint32_t (&r)[4], uint32_t addr) {
    asm volatile("ldmatrix.sync.aligned.m8n8.x4.trans.shared.b16 {%0,%1,%2,%3}, [%4];"
        : "=r"(r[0]), "=r"(r[1]), "=r"(r[2]), "=r"(r[3]) : "r"(addr));
}
__device__ __forceinline__ void mma16816(float (&d)[4], const uint32_t* a,
                                         const uint32_t* b) {
    asm volatile("mma.sync.aligned.m16n8k16.row.col.f32.f16.f16.f32 "
        "{%0,%1,%2,%3}, {%4,%5,%6,%7}, {%8,%9}, {%0,%1,%2,%3};"
        : "+f"(d[0]), "+f"(d[1]), "+f"(d[2]), "+f"(d[3])
        : "r"(a[0]), "r"(a[1]), "r"(a[2]), "r"(a[3]), "r"(b[0]), "r"(b[1]));
}
__device__ __forceinline__ uint32_t ex2_h2(float a, float b) {
    __half2 h = __floats2half2_rn(a, b);
    uint32_t in = *(uint32_t*)&h, out;
    asm("ex2.approx.f16x2 %0, %1;" : "=r"(out) : "r"(in));
    return out;
}
#define CP_ASYNC16(dst, src) \
    asm volatile("cp.async.cg.shared.global [%0], [%1], 16;" :: "r"(dst), "l"(src) : "memory")
#define CP_COMMIT() asm volatile("cp.async.commit_group;" ::: "memory")
#define CP_WAIT(n)  asm volatile("cp.async.wait_group %0;" :: "n"(n) : "memory")

// ---------------------------------------------------------------------------
// Kernel 1: prep — x->fp16 + weight transposes (concurrent)
// ---------------------------------------------------------------------------
#define PREP_CONV_BLOCKS  (MROWS*DMODEL/4/256)           // 4096
#define PREP_WT_BLOCKS    (32*32*4)                      // 4096
#define PREP_BLOCKS (PREP_CONV_BLOCKS + PREP_WT_BLOCKS)

__global__ void __launch_bounds__(256) prep_kernel(
    const float* __restrict__ x,
    const float* __restrict__ wq, const float* __restrict__ wk,
    const float* __restrict__ wv, const float* __restrict__ wp)
{
    int bid = blockIdx.x;
    int tid = threadIdx.x;

    if (bid < PREP_CONV_BLOCKS) {
        int i = bid * 256 + tid;
        float4 v = ((const float4*)x)[i];
        ((__half2*)g_xh)[2*i]   = __floats2half2_rn(v.x, v.y);
        ((__half2*)g_xh)[2*i+1] = __floats2half2_rn(v.z, v.w);
    } else {
        int wb = bid - PREP_CONV_BLOCKS;
        int z  = wb >> 10;
        int by = (wb >> 5) & 31;
        int bx = wb & 31;
        const float* W = (z==0) ? wq : (z==1) ? wk : (z==2) ? wv : wp;
        __half* O      = (z==0) ? g_Wq : (z==1) ? g_Wk : (z==2) ? g_Wv : g_Wp;
        __shared__ float t[32][33];
        int kx = bx * 32, ny = by * 32;
        int tx = tid & 31, ty = tid >> 5;
#pragma unroll
        for (int i = 0; i < 4; i++)
            t[ty + i*8][tx] = W[(size_t)(kx + ty + i*8) * DMODEL + ny + tx];
        __syncthreads();
#pragma unroll
        for (int i = 0; i < 4; i++)
            O[(size_t)(ny + ty + i*8) * DMODEL + kx + tx] = __float2half(t[tx][ty + i*8]);
    }
}

// ---------------------------------------------------------------------------
// Kernel 3: HMMA GEMM, CTA 128x128, 4 warps, warp tile 64x64, BK=64,
// 3-stage cp.async pipeline. grid.z slice 0 computes temporal bias when
// `mat` is non-null (hidden under the tensor-bound GEMM slices).
// ---------------------------------------------------------------------------
#define ROWB 128
#define TILEB (128*ROWB)
#define NSTAGE 3
#define GEMM_SMEM (NSTAGE*2*TILEB)  // 96 KB

__device__ __forceinline__ void store2(float* C, size_t idx, float a, float b) {
    float2 v = {a, b}; *(float2*)&C[idx] = v;
}
__device__ __forceinline__ void store2(__half* C, size_t idx, float a, float b) {
    *(__half2*)&C[idx] = __floats2half2_rn(a, b);
}

template <typename TOUT>
__global__ void __launch_bounds__(128, 2) gemm_tc(
    const __half* __restrict__ A,
    const __half* __restrict__ B0, const __half* __restrict__ B1, const __half* __restrict__ B2,
    const float* __restrict__ bi0, const float* __restrict__ bi1, const float* __restrict__ bi2,
    TOUT* __restrict__ C0, TOUT* __restrict__ C1, TOUT* __restrict__ C2,
    const float* __restrict__ mat,
    const float* __restrict__ tw1, const float* __restrict__ tb1,
    const float* __restrict__ tw2, const float* __restrict__ tb2)
{
    extern __shared__ __align__(128) unsigned char sm[];
    int tid  = threadIdx.x;

    // ---- bias slice (z==0 when mat != null): temporal bias precompute ----
    if (mat != nullptr && blockIdx.z == 0) {
        float* sw1 = (float*)sm;
        float* sb1 = sw1 + TBDIM;
        float* sw2 = sb1 + TBDIM;
        if (tid < TBDIM) { sw1[tid] = tw1[tid]; sb1[tid] = tb1[tid]; sw2[tid] = tw2[tid]; }
        __syncthreads();
        float bias0 = tb2[0];
        int bb = blockIdx.y * 8 + blockIdx.x;        // 0..255
        const float E = 2.718281828459045f;
#pragma unroll 1
        for (int it = 0; it < 16; it++) {
            int i4 = (bb * 16 + it) * 128 + tid;
            float4 mv = ((const float4*)mat)[i4];
            float t0 = 1.0f / __logf(E + mv.x);
            float t1 = 1.0f / __logf(E + mv.y);
            float t2 = 1.0f / __logf(E + mv.z);
            float t3 = 1.0f / __logf(E + mv.w);
            float a0 = bias0, a1 = a0, a2 = a0, a3 = a0;
#pragma unroll
            for (int j = 0; j < TBDIM; j++) {
                float w = sw1[j], bb2 = sb1[j], v = sw2[j];
                float h0 = fmaf(t0, w, bb2); h0 = (h0 >= 0.0f) ? h0 : 0.2f * h0;
                float h1 = fmaf(t1, w, bb2); h1 = (h1 >= 0.0f) ? h1 : 0.2f * h1;
                float h2 = fmaf(t2, w, bb2); h2 = (h2 >= 0.0f) ? h2 : 0.2f * h2;
                float h3 = fmaf(t3, w, bb2); h3 = (h3 >= 0.0f) ? h3 : 0.2f * h3;
                a0 = fmaf(h0, v, a0); a1 = fmaf(h1, v, a1);
                a2 = fmaf(h2, v, a2); a3 = fmaf(h3, v, a3);
            }
            float4 r = {a0, a1, a2, a3};
            ((float4*)g_Tb)[i4] = r;
        }
        return;
    }

    int z = blockIdx.z - (mat ? 1 : 0);
    const __half* Bt   = (z==0) ? B0  : (z==1) ? B1  : B2;
    const float*  bias = (z==0) ? bi0 : (z==1) ? bi1 : bi2;
    TOUT*         C    = (z==0) ? C0  : (z==1) ? C1  : C2;

    int lane = tid & 31;
    int wid  = tid >> 5;
    int wm   = (wid & 1) * 64;
    int wn   = (wid >> 1) * 64;
    int m0 = blockIdx.y * 128, n0 = blockIdx.x * 128;

    uint32_t sbase = smem_u32(sm);

    uint32_t swo[8];
    const __half *gA[8], *gB[8];
#pragma unroll
    for (int i = 0; i < 8; i++) {
        int id = tid + i * 128;
        int r = id >> 3, c = id & 7;
        swo[i] = r * ROWB + ((c ^ (r & 7)) * 16);
        gA[i] = A  + (size_t)(m0 + r) * DMODEL + c * 8;
        gB[i] = Bt + (size_t)(n0 + r) * DMODEL + c * 8;
    }

    float acc[4][8][4] = {};
    const int NKT = DMODEL / 64;

#pragma unroll
    for (int pf = 0; pf < 2; pf++) {
        uint32_t ab = sbase + pf * 2 * TILEB;
        int koff = pf * 64;
#pragma unroll
        for (int i = 0; i < 8; i++) {
            CP_ASYNC16(ab + swo[i],         gA[i] + koff);
            CP_ASYNC16(ab + TILEB + swo[i], gB[i] + koff);
        }
        CP_COMMIT();
    }

    int cur = 0;
    for (int kt = 0; kt < NKT; kt++) {
        if (kt == NKT - 1) { CP_WAIT(0); } else { CP_WAIT(1); }
        __syncthreads();

        if (kt + 2 < NKT) {
            uint32_t ab = sbase + ((cur + 2 >= NSTAGE) ? (cur + 2 - NSTAGE) : (cur + 2)) * 2 * TILEB;
            int koff = (kt + 2) * 64;
#pragma unroll
            for (int i = 0; i < 8; i++) {
                CP_ASYNC16(ab + swo[i],         gA[i] + koff);
                CP_ASYNC16(ab + TILEB + swo[i], gB[i] + koff);
            }
            CP_COMMIT();
        }

        uint32_t aBase = sbase + cur * 2 * TILEB;
        uint32_t bBase = aBase + TILEB;

#pragma unroll
        for (int ks = 0; ks < 4; ks++) {
            uint32_t af[4][4];
#pragma unroll
            for (int mf = 0; mf < 4; mf++) {
                int row = wm + mf * 16 + (lane & 15);
                int ch  = 2 * ks + (lane >> 4);
                ldsm_x4(af[mf], aBase + row * ROWB + ((ch ^ (row & 7)) * 16));
            }
            uint32_t bf[4][4];
#pragma unroll
            for (int p = 0; p < 4; p++) {
                int row = wn + p * 16 + (lane & 7) + ((lane >> 4) << 3);
                int ch  = 2 * ks + ((lane >> 3) & 1);
                ldsm_x4(bf[p], bBase + row * ROWB + ((ch ^ (row & 7)) * 16));
            }
#pragma unroll
            for (int mf = 0; mf < 4; mf++)
#pragma unroll
                for (int p = 0; p < 4; p++) {
                    mma16816(acc[mf][2*p],   af[mf], &bf[p][0]);
                    mma16816(acc[mf][2*p+1], af[mf], &bf[p][2]);
                }
        }
        cur = (cur + 1 >= NSTAGE) ? 0 : (cur + 1);
    }

    int g = lane >> 2, t = lane & 3;
#pragma unroll
    for (int mf = 0; mf < 4; mf++) {
        int r0 = m0 + wm + mf * 16 + g;
#pragma unroll
        for (int nf = 0; nf < 8; nf++) {
            int c = n0 + wn + nf * 8 + t * 2;
            float bx = __ldg(&bias[c]), by = __ldg(&bias[c + 1]);
            store2(C, (size_t)r0 * DMODEL + c,       acc[mf][nf][0] + bx, acc[mf][nf][1] + by);
            store2(C, (size_t)(r0 + 8) * DMODEL + c, acc[mf][nf][2] + bx, acc[mf][nf][3] + by);
        }
    }
}

// ---------------------------------------------------------------------------
// Kernel 4: HMMA causal flash attention — triple-buffered K/V, prefetch
// distance 2 (hides L2 tile-load latency), prefetch issued AFTER the top
// barrier so the end-of-body barrier is provably removable: one barrier
// per iteration. Otherwise exact R11 compute.
// ---------------------------------------------------------------------------
#define LOG2E 1.4426950408889634f

__global__ void __launch_bounds__(128) attn_hmma(const int* __restrict__ pm) {
    __shared__ __align__(128) __half Qs[64*64];
    __shared__ __align__(128) __half Ks[3][64*64];
    __shared__ __align__(128) __half Vs[3][64*64];
    __shared__ int spm[3][64];

    int qt = gridDim.x - 1 - blockIdx.x;      // long blocks first
    int h = blockIdx.y, b = blockIdx.z;
    int tid = threadIdx.x, lane = tid & 31, wid = tid >> 5;
    int wrow = wid * 16;
    int q0 = qt * 64;
    int g = lane >> 2, t = lane & 3;

    const __half* Qg = g_Qh + (size_t)b * SEQ * DMODEL + h * DK;
    const __half* Kg = g_Kh + (size_t)b * SEQ * DMODEL + h * DK;
    const __half* Vg = g_Vh + (size_t)b * SEQ * DMODEL + h * DK;
    const float* Tbb = g_Tb + (size_t)b * SEQ * SEQ;

    uint32_t qb = smem_u32(Qs);
    uint32_t kb_[3] = { smem_u32(Ks[0]), smem_u32(Ks[1]), smem_u32(Ks[2]) };
    uint32_t vb_[3] = { smem_u32(Vs[0]), smem_u32(Vs[1]), smem_u32(Vs[2]) };

    // --- preload: group0 = Q + tile0(+pm0); group1 = tile1(+pm1) if present
#pragma unroll
    for (int i = 0; i < 4; i++) {
        int id = tid + i * 128;
        int rr = id >> 3, c = id & 7;
        uint32_t sw = rr * 128 + ((c ^ (rr & 7)) * 16);
        CP_ASYNC16(qb + sw, Qg + (size_t)(q0 + rr) * DMODEL + c * 8);
        CP_ASYNC16(kb_[0] + sw, Kg + (size_t)rr * DMODEL + c * 8);
        CP_ASYNC16(vb_[0] + sw, Vg + (size_t)rr * DMODEL + c * 8);
    }
    if (tid < 16)
        CP_ASYNC16(smem_u32(spm[0]) + tid * 16, pm + b * SEQ + tid * 4);
    CP_COMMIT();
    if (qt >= 1) {
#pragma unroll
        for (int i = 0; i < 4; i++) {
            int id = tid + i * 128;
            int rr = id >> 3, c = id & 7;
            uint32_t sw = rr * 128 + ((c ^ (rr & 7)) * 16);
            CP_ASYNC16(kb_[1] + sw, Kg + (size_t)(64 + rr) * DMODEL + c * 8);
            CP_ASYNC16(vb_[1] + sw, Vg + (size_t)(64 + rr) * DMODEL + c * 8);
        }
        if (tid < 16)
            CP_ASYNC16(smem_u32(spm[1]) + tid * 16, pm + b * SEQ + 64 + tid * 4);
        CP_COMMIT();
    }

    float m0 = NEGINF, m1 = NEGINF, l0 = 0.0f, l1 = 0.0f;
    float o[8][4] = {};
    uint32_t qf[4][4];
    int qgl0 = q0 + wrow + g;
    int qgl1 = qgl0 + 8;

    const float* tb0p = &Tbb[(size_t)qgl0 * SEQ + t * 2];
    const float* tb1p = &Tbb[(size_t)qgl1 * SEQ + t * 2];

    int cur = 0;
    for (int kt = 0; kt <= qt; kt++) {
        if (kt < qt) { CP_WAIT(1); } else { CP_WAIT(0); }
        __syncthreads();   // tile kt visible; all warps done with buffer (kt-1)%3

        // prefetch tile kt+2 into (kt+2)%3 == (kt-1)%3 (safe: body kt-1 done)
        if (kt + 2 <= qt) {
            int nxt = (cur + 2 >= 3) ? (cur + 2 - 3) : (cur + 2);
#pragma unroll
            for (int i = 0; i < 4; i++) {
                int id = tid + i * 128;
                int rr = id >> 3, c = id & 7;
                uint32_t sw = rr * 128 + ((c ^ (rr & 7)) * 16);
                CP_ASYNC16(kb_[nxt] + sw, Kg + (size_t)((kt+2)*64 + rr) * DMODEL + c * 8);
                CP_ASYNC16(vb_[nxt] + sw, Vg + (size_t)((kt+2)*64 + rr) * DMODEL + c * 8);
            }
            if (tid < 16)
                CP_ASYNC16(smem_u32(spm[nxt]) + tid * 16, pm + b * SEQ + (kt+2)*64 + tid * 4);
            CP_COMMIT();
        }

        if (kt == 0) {
#pragma unroll
            for (int ks = 0; ks < 4; ks++) {
                int row = wrow + (lane & 15);
                int ch  = ks * 2 + (lane >> 4);
                ldsm_x4(qf[ks], qb + row * 128 + ((ch ^ (row & 7)) * 16));
            }
        }

        // ---- hoisted Tb loads (latency hidden under S-mma below) ----
        float2 tbr0[8], tbr1[8];
#pragma unroll
        for (int nf = 0; nf < 8; nf++) {
            tbr0[nf] = *(const float2*)&tb0p[kt * 64 + nf * 8];
            tbr1[nf] = *(const float2*)&tb1p[kt * 64 + nf * 8];
        }

        uint32_t kb = kb_[cur], vb = vb_[cur];
        const int* pmc = spm[cur];

        // ---- S = Q K^T ----
        float s[8][4] = {};
#pragma unroll
        for (int ks = 0; ks < 4; ks++) {
#pragma unroll
            for (int p = 0; p < 4; p++) {
                uint32_t bfr[4];
                int row = p * 16 + (lane & 7) + ((lane >> 4) << 3);
                int ch  = ks * 2 + ((lane >> 3) & 1);
                ldsm_x4(bfr, kb + row * 128 + ((ch ^ (row & 7)) * 16));
                mma16816(s[2*p],   qf[ks], &bfr[0]);
                mma16816(s[2*p+1], qf[ks], &bfr[2]);
            }
        }

        // ---- scale + bias + masks + row max ----
        float mx0 = m0, mx1 = m1;
        if (kt == qt) {
#pragma unroll
            for (int nf = 0; nf < 8; nf++) {
                int coll = nf * 8 + t * 2;
                int kg = kt * 64 + coll;
                float v00 = fmaf(s[nf][0], SCALE, tbr0[nf].x);
                float v01 = fmaf(s[nf][1], SCALE, tbr0[nf].y);
                float v10 = fmaf(s[nf][2], SCALE, tbr1[nf].x);
                float v11 = fmaf(s[nf][3], SCALE, tbr1[nf].y);
                bool z0 = (pmc[coll] == 0), z1 = (pmc[coll + 1] == 0);
                if (z0 || kg     > qgl0) v00 = NEGINF;
                if (z1 || kg + 1 > qgl0) v01 = NEGINF;
                if (z0 || kg     > qgl1) v10 = NEGINF;
                if (z1 || kg + 1 > qgl1) v11 = NEGINF;
                s[nf][0] = v00; s[nf][1] = v01; s[nf][2] = v10; s[nf][3] = v11;
                mx0 = fmaxf(mx0, fmaxf(v00, v01));
                mx1 = fmaxf(mx1, fmaxf(v10, v11));
            }
        } else {
#pragma unroll
            for (int nf = 0; nf < 8; nf++) {
                int coll = nf * 8 + t * 2;
                float v00 = fmaf(s[nf][0], SCALE, tbr0[nf].x);
                float v01 = fmaf(s[nf][1], SCALE, tbr0[nf].y);
                float v10 = fmaf(s[nf][2], SCALE, tbr1[nf].x);
                float v11 = fmaf(s[nf][3], SCALE, tbr1[nf].y);
                if (pmc[coll] == 0)     { v00 = NEGINF; v10 = NEGINF; }
                if (pmc[coll + 1] == 0) { v01 = NEGINF; v11 = NEGINF; }
                s[nf][0] = v00; s[nf][1] = v01; s[nf][2] = v10; s[nf][3] = v11;
                mx0 = fmaxf(mx0, fmaxf(v00, v01));
                mx1 = fmaxf(mx1, fmaxf(v10, v11));
            }
        }
        mx0 = fmaxf(mx0, __shfl_xor_sync(0xffffffffu, mx0, 1));
        mx0 = fmaxf(mx0, __shfl_xor_sync(0xffffffffu, mx0, 2));
        mx1 = fmaxf(mx1, __shfl_xor_sync(0xffffffffu, mx1, 1));
        mx1 = fmaxf(mx1, __shfl_xor_sync(0xffffffffu, mx1, 2));

        float corr0 = __expf(m0 - mx0);
        float corr1 = __expf(m1 - mx1);
        m0 = mx0; m1 = mx1;

        // ---- exponentiate (packed fp16 ex2) -> P frags + row sums ----
        float mxl0 = mx0 * LOG2E, mxl1 = mx1 * LOG2E;
        float sum0 = 0.0f, sum1 = 0.0f;
        uint32_t pa[4][4];
#pragma unroll
        for (int nf = 0; nf < 8; nf++) {
            uint32_t p0 = ex2_h2(fmaf(s[nf][0], LOG2E, -mxl0),
                                 fmaf(s[nf][1], LOG2E, -mxl0));
            uint32_t p1 = ex2_h2(fmaf(s[nf][2], LOG2E, -mxl1),
                                 fmaf(s[nf][3], LOG2E, -mxl1));
            pa[nf >> 1][(nf & 1) * 2 + 0] = p0;
            pa[nf >> 1][(nf & 1) * 2 + 1] = p1;
            float2 f0 = __half22float2(*(__half2*)&p0);
            float2 f1 = __half22float2(*(__half2*)&p1);
            sum0 += f0.x + f0.y;
            sum1 += f1.x + f1.y;
        }
        sum0 += __shfl_xor_sync(0xffffffffu, sum0, 1);
        sum0 += __shfl_xor_sync(0xffffffffu, sum0, 2);
        sum1 += __shfl_xor_sync(0xffffffffu, sum1, 1);
        sum1 += __shfl_xor_sync(0xffffffffu, sum1, 2);
        l0 = l0 * corr0 + sum0;
        l1 = l1 * corr1 + sum1;

#pragma unroll
        for (int nf = 0; nf < 8; nf++) {
            o[nf][0] *= corr0; o[nf][1] *= corr0;
            o[nf][2] *= corr1; o[nf][3] *= corr1;
        }

        // ---- O += P V ----
#pragma unroll
        for (int kk = 0; kk < 4; kk++) {
#pragma unroll
            for (int p = 0; p < 4; p++) {
                uint32_t bfr[4];
                int row = kk * 16 + (lane & 7) + (((lane >> 3) & 1) << 3);
                int ch  = p * 2 + ((lane >> 4) & 1);
                ldsm_x4t(bfr, vb + row * 128 + ((ch ^ (row & 7)) * 16));
                mma16816(o[2*p],   pa[kk], &bfr[0]);
                mma16816(o[2*p+1], pa[kk], &bfr[2]);
            }
        }
        cur = (cur + 1 >= 3) ? 0 : (cur + 1);
        // no end-of-body barrier: buffer reuse is protected by the top
        // barrier of iteration kt+2 (prefetch issued after it).
    }

    float inv0 = 1.0f / l0, inv1 = 1.0f / l1;
    __half* Og = g_Oh + (size_t)b * SEQ * DMODEL + h * DK;
#pragma unroll
    for (int nf = 0; nf < 8; nf++) {
        int coll = nf * 8 + t * 2;
        *(__half2*)&Og[(size_t)(q0 + wrow + g) * DMODEL + coll] =
            __floats2half2_rn(o[nf][0] * inv0, o[nf][1] * inv0);
        *(__half2*)&Og[(size_t)(q0 + wrow + g + 8) * DMODEL + coll] =
            __floats2half2_rn(o[nf][2] * inv1, o[nf][3] * inv1);
    }
}

// ---------------------------------------------------------------------------
extern "C" void kernel_launch(void* const* d_in, const int* in_sizes, int n_in,
                              void* d_out, int out_size) {
    const float* x      = (const float*)d_in[0];
    const int*   pm     = (const int*)  d_in[1];
    const float* mat    = (const float*)d_in[2];
    const float* wq     = (const float*)d_in[3];
    const float* bq     = (const float*)d_in[4];
    const float* wk     = (const float*)d_in[5];
    const float* bk     = (const float*)d_in[6];
    const float* wv     = (const float*)d_in[7];
    const float* bv     = (const float*)d_in[8];
    const float* w_proj = (const float*)d_in[9];
    const float* b_proj = (const float*)d_in[10];
    const float* w_tb1  = (const float*)d_in[11];
    const float* b_tb1  = (const float*)d_in[12];
    const float* w_tb2  = (const float*)d_in[13];
    const float* b_tb2  = (const float*)d_in[14];
    float* out = (float*)d_out;

    __half *xh, *Oh, *Wq, *Wk, *Wv, *Wp, *Qh, *Kh, *Vh;
    cudaGetSymbolAddress((void**)&xh, g_xh);
    cudaGetSymbolAddress((void**)&Oh, g_Oh);
    cudaGetSymbolAddress((void**)&Wq, g_Wq);
    cudaGetSymbolAddress((void**)&Wk, g_Wk);
    cudaGetSymbolAddress((void**)&Wv, g_Wv);
    cudaGetSymbolAddress((void**)&Wp, g_Wp);
    cudaGetSymbolAddress((void**)&Qh, g_Qh);
    cudaGetSymbolAddress((void**)&Kh, g_Kh);
    cudaGetSymbolAddress((void**)&Vh, g_Vh);

    cudaFuncSetAttribute(gemm_tc<__half>, cudaFuncAttributeMaxDynamicSharedMemorySize, GEMM_SMEM);
    cudaFuncSetAttribute(gemm_tc<float>,  cudaFuncAttributeMaxDynamicSharedMemorySize, GEMM_SMEM);

    // 1) prep: x->fp16 + weight transposes (concurrent)
    prep_kernel<<<PREP_BLOCKS, 256>>>(x, wq, wk, wv, w_proj);

    // 2) QKV projections (HMMA, fp16 out) + temporal bias in grid.z slice 0
    gemm_tc<__half><<<dim3(DMODEL/128, MROWS/128, 4), 128, GEMM_SMEM>>>(
        xh, Wq, Wk, Wv, bq, bk, bv, Qh, Kh, Vh,
        mat, w_tb1, b_tb1, w_tb2, b_tb2);

    // 3) HMMA flash attention (triple-buffered, depth-2 prefetch)
    attn_hmma<<<dim3(SEQ/64, NHEAD, BATCH), 128>>>(pm);

    // 4) output projection (HMMA, fp32 out; no bias slice)
    gemm_tc<float><<<dim3(DMODEL/128, MROWS/128, 1), 128, GEMM_SMEM>>>(
        Oh, Wp, Wp, Wp, b_proj, b_proj, b_proj, out, out, out,
        nullptr, nullptr, nullptr, nullptr, nullptr);
}